// round 1
// baseline (speedup 1.0000x reference)
#include <cuda_runtime.h>
#include <cuda_bf16.h>
#include <math.h>

// Problem constants
#define BB 4
#define NN 16384
#define NVV 16384
#define DD 256
#define NHH 8
#define PP 4
// HD = 32, feature map 128x128

// Scratch (device globals — no runtime allocation allowed)
__device__ float g_v[(size_t)BB * NVV * DD];        // 64 MB: value projection
__device__ float g_weighted[(size_t)BB * NN * DD];  // 64 MB: gathered+weighted
__device__ float g_off[(size_t)BB * NN * 64];       // 16 MB: sampling offsets
__device__ float g_attn[(size_t)BB * NN * 32];      //  8 MB: attn logits

// ---------------------------------------------------------------------------
// Generic tiled SGEMM with bias: C[M,N] = A[M,K] @ B[K,N] + bias[N]
// Row-major everywhere. M % BM == 0, N % BN == 0, K % BK == 0 for our shapes.
// ---------------------------------------------------------------------------
template <int BM, int BN, int BK, int TM, int TN>
__global__ void sgemm_bias(const float* __restrict__ A,
                           const float* __restrict__ Bm,
                           const float* __restrict__ bias,
                           float* __restrict__ C,
                           int M, int N, int K) {
    constexpr int THREADS = (BM / TM) * (BN / TN);
    __shared__ float As[BK][BM];
    __shared__ float Bs[BK][BN];

    const int tid = threadIdx.x;
    const int tx = tid % (BN / TN);
    const int ty = tid / (BN / TN);
    const int rowBase = blockIdx.y * BM;
    const int colBase = blockIdx.x * BN;

    float acc[TM][TN];
#pragma unroll
    for (int i = 0; i < TM; i++)
#pragma unroll
        for (int j = 0; j < TN; j++) acc[i][j] = 0.0f;

    for (int k0 = 0; k0 < K; k0 += BK) {
        // Load A tile (BM x BK), transpose into As[k][m]
#pragma unroll 4
        for (int i = tid * 4; i < BM * BK; i += THREADS * 4) {
            int r = i / BK, c = i % BK;
            float4 v4 = *reinterpret_cast<const float4*>(
                &A[(size_t)(rowBase + r) * K + k0 + c]);
            As[c + 0][r] = v4.x;
            As[c + 1][r] = v4.y;
            As[c + 2][r] = v4.z;
            As[c + 3][r] = v4.w;
        }
        // Load B tile (BK x BN)
#pragma unroll 4
        for (int i = tid * 4; i < BK * BN; i += THREADS * 4) {
            int r = i / BN, c = i % BN;
            *reinterpret_cast<float4*>(&Bs[r][c]) =
                *reinterpret_cast<const float4*>(
                    &Bm[(size_t)(k0 + r) * N + colBase + c]);
        }
        __syncthreads();

#pragma unroll
        for (int k = 0; k < BK; k++) {
            float aR[TM], bR[TN];
#pragma unroll
            for (int i = 0; i < TM; i++) aR[i] = As[k][ty * TM + i];
#pragma unroll
            for (int j = 0; j < TN; j++) bR[j] = Bs[k][tx * TN + j];
#pragma unroll
            for (int i = 0; i < TM; i++)
#pragma unroll
                for (int j = 0; j < TN; j++) acc[i][j] += aR[i] * bR[j];
        }
        __syncthreads();
    }

#pragma unroll
    for (int i = 0; i < TM; i++) {
        int r = rowBase + ty * TM + i;
#pragma unroll
        for (int j = 0; j < TN; j++) {
            int c = colBase + tx * TN + j;
            C[(size_t)r * N + c] = acc[i][j] + bias[c];
        }
    }
}

// ---------------------------------------------------------------------------
// Sampling kernel: one warp per query.
// lane -> (h = lane>>2, p = lane&3). Softmax over P within each quad,
// nearest-neighbor index per (h,p), then per-head gather of HD=32 floats
// (lane = hd) with weights broadcast via shfl.
// ---------------------------------------------------------------------------
__global__ void sample_kernel(const float* __restrict__ refp,   // (B,N,2)
                              const float* __restrict__ off,    // (B,N,64)
                              const float* __restrict__ attnl,  // (B,N,32)
                              const float* __restrict__ v,      // (B,NV,256)
                              float* __restrict__ outw)         // (B,N,256)
{
    const int warpsPerBlock = blockDim.x >> 5;
    const int q = blockIdx.x * warpsPerBlock + (threadIdx.x >> 5);
    const int lane = threadIdx.x & 31;
    if (q >= BB * NN) return;
    const int b = q >> 14;  // N == 16384

    // ---- per-(h,p) work on each lane ----
    float logit = attnl[(size_t)q * 32 + lane];
    float m = logit;
    m = fmaxf(m, __shfl_xor_sync(0xffffffffu, m, 1));
    m = fmaxf(m, __shfl_xor_sync(0xffffffffu, m, 2));
    float e = expf(logit - m);
    float s = e;
    s += __shfl_xor_sync(0xffffffffu, s, 1);
    s += __shfl_xor_sync(0xffffffffu, s, 2);
    float w = e / s;

    float rx = refp[(size_t)q * 2 + 0];
    float ry = refp[(size_t)q * 2 + 1];
    float ox = off[(size_t)q * 64 + lane * 2 + 0];
    float oy = off[(size_t)q * 64 + lane * 2 + 1];
    // match reference op ordering exactly
    float lx = (rx + ox) * 2.0f - 1.0f;
    float ly = (ry + oy) * 2.0f - 1.0f;
    float fx = (lx + 1.0f) * 64.0f - 0.5f;  // Ww*0.5 = 64
    float fy = (ly + 1.0f) * 64.0f - 0.5f;  // Hh*0.5 = 64
    float ixf = rintf(fx);                  // round half-to-even, like jnp.round
    float iyf = rintf(fy);
    bool valid = (ixf >= 0.0f) && (ixf < 128.0f) && (iyf >= 0.0f) && (iyf < 128.0f);
    int flat = valid ? ((int)iyf * 128 + (int)ixf) : 0;
    float wv = valid ? w : 0.0f;

    // ---- gather phase: lane = hd ----
    const float* vb = v + (size_t)b * NVV * DD;
    const size_t outBase = (size_t)q * DD;
#pragma unroll
    for (int h = 0; h < NHH; h++) {
        float acc = 0.0f;
#pragma unroll
        for (int p = 0; p < PP; p++) {
            int src = h * 4 + p;
            float ww = __shfl_sync(0xffffffffu, wv, src);
            int fl = __shfl_sync(0xffffffffu, flat, src);
            if (ww != 0.0f) {
                acc += ww * vb[(size_t)fl * DD + h * 32 + lane];
            }
        }
        outw[outBase + h * 32 + lane] = acc;
    }
}

// ---------------------------------------------------------------------------
extern "C" void kernel_launch(void* const* d_in, const int* in_sizes, int n_in,
                              void* d_out, int out_size) {
    const float* query  = (const float*)d_in[0];
    const float* refp   = (const float*)d_in[1];
    const float* value  = (const float*)d_in[2];
    const float* W_off  = (const float*)d_in[3];
    const float* b_off  = (const float*)d_in[4];
    const float* W_attn = (const float*)d_in[5];
    const float* b_attn = (const float*)d_in[6];
    const float* W_v    = (const float*)d_in[7];
    const float* b_v    = (const float*)d_in[8];
    const float* W_out  = (const float*)d_in[9];
    const float* b_out  = (const float*)d_in[10];
    float* out = (float*)d_out;

    float *gv = nullptr, *gw = nullptr, *go = nullptr, *ga = nullptr;
    cudaGetSymbolAddress((void**)&gv, g_v);
    cudaGetSymbolAddress((void**)&gw, g_weighted);
    cudaGetSymbolAddress((void**)&go, g_off);
    cudaGetSymbolAddress((void**)&ga, g_attn);

    const int M = BB * NN;  // 65536
    const int K = DD;       // 256

    // 1. v = value @ W_v + b_v        (65536 x 256 x 256)
    sgemm_bias<128, 128, 16, 8, 8>
        <<<dim3(256 / 128, M / 128), 256>>>(value, W_v, b_v, gv, M, 256, K);

    // 2. off = query @ W_off + b_off  (65536 x 64 x 256)
    sgemm_bias<128, 64, 16, 8, 4>
        <<<dim3(1, M / 128), 256>>>(query, W_off, b_off, go, M, 64, K);

    // 3. attn logits = query @ W_attn + b_attn (65536 x 32 x 256)
    sgemm_bias<128, 32, 16, 8, 2>
        <<<dim3(1, M / 128), 256>>>(query, W_attn, b_attn, ga, M, 32, K);

    // 4. softmax + nearest-sample gather + weighted sum -> weighted (B,N,D)
    {
        int warpsPerBlock = 8;  // 256 threads
        int blocks = (M + warpsPerBlock - 1) / warpsPerBlock;
        sample_kernel<<<blocks, warpsPerBlock * 32>>>(refp, go, ga, gv, gw);
    }

    // 5. out = weighted @ W_out + b_out (65536 x 256 x 256)
    sgemm_bias<128, 128, 16, 8, 8>
        <<<dim3(256 / 128, M / 128), 256>>>(gw, W_out, b_out, out, M, 256, K);
}

// round 4
// speedup vs baseline: 2.7809x; 2.7809x over previous
#include <cuda_runtime.h>
#include <cuda_bf16.h>
#include <math.h>
#include <stdint.h>

// Problem constants
#define BB 4
#define NN 16384
#define NVV 16384
#define DD 256
#define NHH 8
#define PP 4

// Scratch (device globals — no runtime allocation allowed)
__device__ float g_v[(size_t)BB * NVV * DD];        // 64 MB
__device__ float g_weighted[(size_t)BB * NN * DD];  // 64 MB
__device__ float g_off[(size_t)BB * NN * 64];       // 16 MB
__device__ float g_attn[(size_t)BB * NN * 32];      //  8 MB
// bf16-split, transposed weights: [n][k] (K-major), hi/lo parts
__device__ __nv_bfloat16 g_wv_hi[DD * DD], g_wv_lo[DD * DD];
__device__ __nv_bfloat16 g_wo_hi[DD * DD], g_wo_lo[DD * DD];

__device__ __forceinline__ uint32_t smem_u32(const void* p) {
    uint32_t a;
    asm("{ .reg .u64 t; cvta.to.shared.u64 t, %1; cvt.u32.u64 %0, t; }"
        : "=r"(a) : "l"(p));
    return a;
}

// ldmatrix x4 (A operand, 16x16 bf16 tile)
#define LDSM_X4(r0, r1, r2, r3, addr)                                          \
    asm volatile("ldmatrix.sync.aligned.m8n8.x4.shared.b16 {%0,%1,%2,%3}, [%4];" \
                 : "=r"(r0), "=r"(r1), "=r"(r2), "=r"(r3) : "r"(addr))
// ldmatrix x2 NON-trans (B operand from [n][k] storage:
// thread t gets stored[n=t/4][k=(t%4)*2+{0,1}] == mma col-major B fragment)
#define LDSM_X2(r0, r1, addr)                                                  \
    asm volatile("ldmatrix.sync.aligned.m8n8.x2.shared.b16 {%0,%1}, [%2];"     \
                 : "=r"(r0), "=r"(r1) : "r"(addr))
// mma m16n8k16 bf16 -> fp32
#define MMA16816(acc, a, b)                                                    \
    asm volatile(                                                              \
        "mma.sync.aligned.m16n8k16.row.col.f32.bf16.bf16.f32 "                 \
        "{%0,%1,%2,%3}, {%4,%5,%6,%7}, {%8,%9}, {%0,%1,%2,%3};"                \
        : "+f"((acc)[0]), "+f"((acc)[1]), "+f"((acc)[2]), "+f"((acc)[3])       \
        : "r"((a)[0]), "r"((a)[1]), "r"((a)[2]), "r"((a)[3]),                  \
          "r"((b)[0]), "r"((b)[1]))

// ===========================================================================
// Weight prep: W [K=256][Nw] fp32 row-major -> hi/lo bf16 in [n][k] layout
// ===========================================================================
__global__ void prep_weight(const float* __restrict__ W,
                            __nv_bfloat16* __restrict__ hi,
                            __nv_bfloat16* __restrict__ lo, int Nw) {
    int id = blockIdx.x * 256 + threadIdx.x;  // id = n*256 + k
    int n = id >> 8, k = id & 255;
    float v = W[(size_t)k * Nw + n];
    __nv_bfloat16 h = __float2bfloat16_rn(v);
    hi[id] = h;
    lo[id] = __float2bfloat16_rn(v - __bfloat162float(h));
}

// ===========================================================================
// Tensor-core GEMM via mma.sync (bf16x3 split):
//   C[M,256] = A[M,256](fp32) @ W[256,256] + bias
// CTA tile 128x128 (grid 2 x M/128), 8 warps (warp tile 64x32),
// K chunked by 64. Smem stride 72 halves: conflict-free, 16B-aligned rows.
// ===========================================================================
#define LDS_STRIDE 72
__global__ void __launch_bounds__(256, 2) gemm_mma(
    const float* __restrict__ A,
    const __nv_bfloat16* __restrict__ Bhi,
    const __nv_bfloat16* __restrict__ Blo,
    const float* __restrict__ bias,
    float* __restrict__ C) {
    extern __shared__ __nv_bfloat16 sm[];
    __nv_bfloat16* As_hi = sm;                        // 128*72
    __nv_bfloat16* As_lo = As_hi + 128 * LDS_STRIDE;
    __nv_bfloat16* Bs_hi = As_lo + 128 * LDS_STRIDE;
    __nv_bfloat16* Bs_lo = Bs_hi + 128 * LDS_STRIDE;
    float* s_bias = reinterpret_cast<float*>(Bs_lo + 128 * LDS_STRIDE);

    const int tid = threadIdx.x;
    const int wid = tid >> 5;
    const int lane = tid & 31;
    const int rowBase = blockIdx.y * 128;
    const int colBase = blockIdx.x * 128;
    const int warpRow = (wid >> 2) * 64;  // 0 or 64
    const int warpCol = (wid & 3) * 32;   // 0,32,64,96

    if (tid < 128) s_bias[tid] = bias[colBase + tid];

    float acc[4][4][4];
#pragma unroll
    for (int i = 0; i < 4; i++)
#pragma unroll
        for (int j = 0; j < 4; j++)
#pragma unroll
            for (int r = 0; r < 4; r++) acc[i][j][r] = 0.0f;

    // ldmatrix source addresses (fixed per thread; k-offset added per step)
    const int a_row = warpRow + (lane & 7) + (lane & 8);
    const int a_col = (lane >> 4) * 8;
    const uint32_t a_hi_base = smem_u32(As_hi) + (a_row * LDS_STRIDE + a_col) * 2;
    const uint32_t a_lo_base = smem_u32(As_lo) + (a_row * LDS_STRIDE + a_col) * 2;
    const int b_row = warpCol + (lane & 7);
    const int b_col = ((lane >> 3) & 1) * 8;
    const uint32_t b_hi_base = smem_u32(Bs_hi) + (b_row * LDS_STRIDE + b_col) * 2;
    const uint32_t b_lo_base = smem_u32(Bs_lo) + (b_row * LDS_STRIDE + b_col) * 2;

    for (int c = 0; c < 4; c++) {
        const int k0 = c * 64;
        __syncthreads();
        // ---- A chunk: 128x64 fp32 -> hi/lo bf16 ----
#pragma unroll
        for (int it = 0; it < 8; it++) {
            int i = it * 256 + tid;          // 2048 float4 loads
            int row = i >> 4, col = (i & 15) * 4;
            float4 v = *reinterpret_cast<const float4*>(
                &A[(size_t)(rowBase + row) * 256 + k0 + col]);
            __nv_bfloat16 h0 = __float2bfloat16_rn(v.x);
            __nv_bfloat16 h1 = __float2bfloat16_rn(v.y);
            __nv_bfloat16 h2 = __float2bfloat16_rn(v.z);
            __nv_bfloat16 h3 = __float2bfloat16_rn(v.w);
            __nv_bfloat16 l0 = __float2bfloat16_rn(v.x - __bfloat162float(h0));
            __nv_bfloat16 l1 = __float2bfloat16_rn(v.y - __bfloat162float(h1));
            __nv_bfloat16 l2 = __float2bfloat16_rn(v.z - __bfloat162float(h2));
            __nv_bfloat16 l3 = __float2bfloat16_rn(v.w - __bfloat162float(h3));
            uint2 hw, lw;
            hw.x = (uint32_t)__bfloat16_as_ushort(h0) |
                   ((uint32_t)__bfloat16_as_ushort(h1) << 16);
            hw.y = (uint32_t)__bfloat16_as_ushort(h2) |
                   ((uint32_t)__bfloat16_as_ushort(h3) << 16);
            lw.x = (uint32_t)__bfloat16_as_ushort(l0) |
                   ((uint32_t)__bfloat16_as_ushort(l1) << 16);
            lw.y = (uint32_t)__bfloat16_as_ushort(l2) |
                   ((uint32_t)__bfloat16_as_ushort(l3) << 16);
            *reinterpret_cast<uint2*>(&As_hi[row * LDS_STRIDE + col]) = hw;
            *reinterpret_cast<uint2*>(&As_lo[row * LDS_STRIDE + col]) = lw;
        }
        // ---- B chunk: 128(n) x 64(k) bf16 hi/lo (preconverted) ----
#pragma unroll
        for (int it = 0; it < 4; it++) {
            int i = it * 256 + tid;          // 1024 uint4 loads
            int n = i >> 3, col = (i & 7) * 8;
            uint4 hv = *reinterpret_cast<const uint4*>(
                &Bhi[(size_t)(colBase + n) * 256 + k0 + col]);
            uint4 lv = *reinterpret_cast<const uint4*>(
                &Blo[(size_t)(colBase + n) * 256 + k0 + col]);
            *reinterpret_cast<uint4*>(&Bs_hi[n * LDS_STRIDE + col]) = hv;
            *reinterpret_cast<uint4*>(&Bs_lo[n * LDS_STRIDE + col]) = lv;
        }
        __syncthreads();

        // ---- compute: 4 k16 steps ----
#pragma unroll
        for (int ks = 0; ks < 4; ks++) {
            const uint32_t kof = ks * 16 * 2;  // byte offset
            uint32_t bh[4][2], bl[4][2];
#pragma unroll
            for (int j = 0; j < 4; j++) {
                LDSM_X2(bh[j][0], bh[j][1], b_hi_base + j * (8 * LDS_STRIDE * 2) + kof);
                LDSM_X2(bl[j][0], bl[j][1], b_lo_base + j * (8 * LDS_STRIDE * 2) + kof);
            }
#pragma unroll
            for (int i = 0; i < 4; i++) {
                uint32_t ah[4], al[4];
                LDSM_X4(ah[0], ah[1], ah[2], ah[3],
                        a_hi_base + i * (16 * LDS_STRIDE * 2) + kof);
                LDSM_X4(al[0], al[1], al[2], al[3],
                        a_lo_base + i * (16 * LDS_STRIDE * 2) + kof);
#pragma unroll
                for (int j = 0; j < 4; j++) {
                    MMA16816(acc[i][j], ah, bh[j]);
                    MMA16816(acc[i][j], ah, bl[j]);
                    MMA16816(acc[i][j], al, bh[j]);
                }
            }
        }
    }

    // ---- epilogue ----
    const int g = lane >> 2, c2 = (lane & 3) * 2;
#pragma unroll
    for (int i = 0; i < 4; i++) {
        int r0 = rowBase + warpRow + i * 16 + g;
#pragma unroll
        for (int j = 0; j < 4; j++) {
            int col = warpCol + j * 8 + c2;
            float b0 = s_bias[col], b1 = s_bias[col + 1];
            float2 o0 = make_float2(acc[i][j][0] + b0, acc[i][j][1] + b1);
            float2 o1 = make_float2(acc[i][j][2] + b0, acc[i][j][3] + b1);
            *reinterpret_cast<float2*>(&C[(size_t)r0 * 256 + colBase + col]) = o0;
            *reinterpret_cast<float2*>(&C[(size_t)(r0 + 8) * 256 + colBase + col]) = o1;
        }
    }
}

// ===========================================================================
// fp32 SGEMM (exact — off/attn projections are nearest-index flip-sensitive)
// ===========================================================================
template <int BM, int BN, int BK, int TM, int TN>
__global__ void sgemm_bias(const float* __restrict__ A,
                           const float* __restrict__ Bm,
                           const float* __restrict__ bias,
                           float* __restrict__ C,
                           int M, int N, int K) {
    constexpr int THREADS = (BM / TM) * (BN / TN);
    __shared__ float As[BK][BM];
    __shared__ float Bs[BK][BN];

    const int tid = threadIdx.x;
    const int tx = tid % (BN / TN);
    const int ty = tid / (BN / TN);
    const int rowBase = blockIdx.y * BM;
    const int colBase = blockIdx.x * BN;

    float acc[TM][TN];
#pragma unroll
    for (int i = 0; i < TM; i++)
#pragma unroll
        for (int j = 0; j < TN; j++) acc[i][j] = 0.0f;

    for (int k0 = 0; k0 < K; k0 += BK) {
#pragma unroll 4
        for (int i = tid * 4; i < BM * BK; i += THREADS * 4) {
            int r = i / BK, c = i % BK;
            float4 v4 = *reinterpret_cast<const float4*>(
                &A[(size_t)(rowBase + r) * K + k0 + c]);
            As[c + 0][r] = v4.x;
            As[c + 1][r] = v4.y;
            As[c + 2][r] = v4.z;
            As[c + 3][r] = v4.w;
        }
#pragma unroll 4
        for (int i = tid * 4; i < BK * BN; i += THREADS * 4) {
            int r = i / BN, c = i % BN;
            *reinterpret_cast<float4*>(&Bs[r][c]) =
                *reinterpret_cast<const float4*>(
                    &Bm[(size_t)(k0 + r) * N + colBase + c]);
        }
        __syncthreads();

#pragma unroll
        for (int k = 0; k < BK; k++) {
            float aR[TM], bR[TN];
#pragma unroll
            for (int i = 0; i < TM; i++) aR[i] = As[k][ty * TM + i];
#pragma unroll
            for (int j = 0; j < TN; j++) bR[j] = Bs[k][tx * TN + j];
#pragma unroll
            for (int i = 0; i < TM; i++)
#pragma unroll
                for (int j = 0; j < TN; j++) acc[i][j] += aR[i] * bR[j];
        }
        __syncthreads();
    }

#pragma unroll
    for (int i = 0; i < TM; i++) {
        int r = rowBase + ty * TM + i;
#pragma unroll
        for (int j = 0; j < TN; j++) {
            int c = colBase + tx * TN + j;
            C[(size_t)r * N + c] = acc[i][j] + bias[c];
        }
    }
}

// ---------------------------------------------------------------------------
// Sampling kernel (unchanged)
// ---------------------------------------------------------------------------
__global__ void sample_kernel(const float* __restrict__ refp,
                              const float* __restrict__ off,
                              const float* __restrict__ attnl,
                              const float* __restrict__ v,
                              float* __restrict__ outw) {
    const int warpsPerBlock = blockDim.x >> 5;
    const int q = blockIdx.x * warpsPerBlock + (threadIdx.x >> 5);
    const int lane = threadIdx.x & 31;
    if (q >= BB * NN) return;
    const int b = q >> 14;

    float logit = attnl[(size_t)q * 32 + lane];
    float m = logit;
    m = fmaxf(m, __shfl_xor_sync(0xffffffffu, m, 1));
    m = fmaxf(m, __shfl_xor_sync(0xffffffffu, m, 2));
    float e = expf(logit - m);
    float s = e;
    s += __shfl_xor_sync(0xffffffffu, s, 1);
    s += __shfl_xor_sync(0xffffffffu, s, 2);
    float w = e / s;

    float rx = refp[(size_t)q * 2 + 0];
    float ry = refp[(size_t)q * 2 + 1];
    float ox = off[(size_t)q * 64 + lane * 2 + 0];
    float oy = off[(size_t)q * 64 + lane * 2 + 1];
    float lx = (rx + ox) * 2.0f - 1.0f;
    float ly = (ry + oy) * 2.0f - 1.0f;
    float fx = (lx + 1.0f) * 64.0f - 0.5f;
    float fy = (ly + 1.0f) * 64.0f - 0.5f;
    float ixf = rintf(fx);
    float iyf = rintf(fy);
    bool valid = (ixf >= 0.0f) && (ixf < 128.0f) && (iyf >= 0.0f) && (iyf < 128.0f);
    int flat = valid ? ((int)iyf * 128 + (int)ixf) : 0;
    float wv = valid ? w : 0.0f;

    const float* vb = v + (size_t)b * NVV * DD;
    const size_t outBase = (size_t)q * DD;
#pragma unroll
    for (int h = 0; h < NHH; h++) {
        float acc = 0.0f;
#pragma unroll
        for (int p = 0; p < PP; p++) {
            int src = h * 4 + p;
            float ww = __shfl_sync(0xffffffffu, wv, src);
            int fl = __shfl_sync(0xffffffffu, flat, src);
            if (ww != 0.0f) {
                acc += ww * vb[(size_t)fl * DD + h * 32 + lane];
            }
        }
        outw[outBase + h * 32 + lane] = acc;
    }
}

// ---------------------------------------------------------------------------
extern "C" void kernel_launch(void* const* d_in, const int* in_sizes, int n_in,
                              void* d_out, int out_size) {
    const float* query  = (const float*)d_in[0];
    const float* refp   = (const float*)d_in[1];
    const float* value  = (const float*)d_in[2];
    const float* W_off  = (const float*)d_in[3];
    const float* b_off  = (const float*)d_in[4];
    const float* W_attn = (const float*)d_in[5];
    const float* b_attn = (const float*)d_in[6];
    const float* W_v    = (const float*)d_in[7];
    const float* b_v    = (const float*)d_in[8];
    const float* W_out  = (const float*)d_in[9];
    const float* b_out  = (const float*)d_in[10];
    float* out = (float*)d_out;

    float *gv = nullptr, *gw = nullptr, *go = nullptr, *ga = nullptr;
    __nv_bfloat16 *wvh = nullptr, *wvl = nullptr, *woh = nullptr, *wol = nullptr;
    cudaGetSymbolAddress((void**)&gv, g_v);
    cudaGetSymbolAddress((void**)&gw, g_weighted);
    cudaGetSymbolAddress((void**)&go, g_off);
    cudaGetSymbolAddress((void**)&ga, g_attn);
    cudaGetSymbolAddress((void**)&wvh, g_wv_hi);
    cudaGetSymbolAddress((void**)&wvl, g_wv_lo);
    cudaGetSymbolAddress((void**)&woh, g_wo_hi);
    cudaGetSymbolAddress((void**)&wol, g_wo_lo);

    const int M = BB * NN;  // 65536
    // smem: 4 tiles of 128*72 bf16 + 128 floats of bias
    const int SMEM = 4 * 128 * LDS_STRIDE * 2 + 128 * 4;  // 74240
    cudaFuncSetAttribute(gemm_mma, cudaFuncAttributeMaxDynamicSharedMemorySize,
                         SMEM);

    // 0. prep bf16-split transposed weights
    prep_weight<<<256, 256>>>(W_v, wvh, wvl, 256);
    prep_weight<<<256, 256>>>(W_out, woh, wol, 256);

    // 1. v = value @ W_v + b_v (tensor cores, bf16x3)
    gemm_mma<<<dim3(2, M / 128), 256, SMEM>>>(value, wvh, wvl, b_v, gv);

    // 2/3. off / attn projections — EXACT fp32 (flip-sensitive indices)
    sgemm_bias<128, 64, 16, 8, 4>
        <<<dim3(1, M / 128), 256>>>(query, W_off, b_off, go, M, 64, 256);
    sgemm_bias<128, 32, 16, 8, 2>
        <<<dim3(1, M / 128), 256>>>(query, W_attn, b_attn, ga, M, 32, 256);

    // 4. softmax + nearest gather + weighted sum
    sample_kernel<<<M / 8, 256>>>(refp, go, ga, gv, gw);

    // 5. out = weighted @ W_out + b_out (tensor cores, bf16x3)
    gemm_mma<<<dim3(2, M / 128), 256, SMEM>>>(gw, woh, wol, b_out, out);
}

// round 5
// speedup vs baseline: 2.9540x; 1.0623x over previous
#include <cuda_runtime.h>
#include <cuda_bf16.h>
#include <math.h>
#include <stdint.h>

// Problem constants
#define BB 4
#define NN 16384
#define NVV 16384
#define DD 256
#define NHH 8
#define PP 4

// Scratch (device globals — no runtime allocation allowed)
__device__ float g_v[(size_t)BB * NVV * DD];        // 64 MB
__device__ float g_weighted[(size_t)BB * NN * DD];  // 64 MB
__device__ float g_proj[(size_t)BB * NN * 96];      // 24 MB: off(64)+attn(32)
// bf16-split, transposed weights: [n][k] (K-major), hi/lo parts
__device__ __nv_bfloat16 g_wv_hi[DD * DD], g_wv_lo[DD * DD];
__device__ __nv_bfloat16 g_wo_hi[DD * DD], g_wo_lo[DD * DD];

__device__ __forceinline__ uint32_t smem_u32(const void* p) {
    uint32_t a;
    asm("{ .reg .u64 t; cvta.to.shared.u64 t, %1; cvt.u32.u64 %0, t; }"
        : "=r"(a) : "l"(p));
    return a;
}

// ldmatrix x4 (A operand, 16x16 bf16 tile)
#define LDSM_X4(r0, r1, r2, r3, addr)                                          \
    asm volatile("ldmatrix.sync.aligned.m8n8.x4.shared.b16 {%0,%1,%2,%3}, [%4];" \
                 : "=r"(r0), "=r"(r1), "=r"(r2), "=r"(r3) : "r"(addr))
// ldmatrix x2 NON-trans (B operand from [n][k] storage)
#define LDSM_X2(r0, r1, addr)                                                  \
    asm volatile("ldmatrix.sync.aligned.m8n8.x2.shared.b16 {%0,%1}, [%2];"     \
                 : "=r"(r0), "=r"(r1) : "r"(addr))
// mma m16n8k16 bf16 -> fp32
#define MMA16816(acc, a, b)                                                    \
    asm volatile(                                                              \
        "mma.sync.aligned.m16n8k16.row.col.f32.bf16.bf16.f32 "                 \
        "{%0,%1,%2,%3}, {%4,%5,%6,%7}, {%8,%9}, {%0,%1,%2,%3};"                \
        : "+f"((acc)[0]), "+f"((acc)[1]), "+f"((acc)[2]), "+f"((acc)[3])       \
        : "r"((a)[0]), "r"((a)[1]), "r"((a)[2]), "r"((a)[3]),                  \
          "r"((b)[0]), "r"((b)[1]))

// ===========================================================================
// Weight prep: W [K=256][Nw] fp32 row-major -> hi/lo bf16 in [n][k] layout
// ===========================================================================
__global__ void prep_weight(const float* __restrict__ W,
                            __nv_bfloat16* __restrict__ hi,
                            __nv_bfloat16* __restrict__ lo, int Nw) {
    int id = blockIdx.x * 256 + threadIdx.x;  // id = n*256 + k
    int n = id >> 8, k = id & 255;
    float v = W[(size_t)k * Nw + n];
    __nv_bfloat16 h = __float2bfloat16_rn(v);
    hi[id] = h;
    lo[id] = __float2bfloat16_rn(v - __bfloat162float(h));
}

// ===========================================================================
// Tensor-core GEMM via mma.sync (bf16x3 split) — unchanged from round 4
// ===========================================================================
#define LDS_STRIDE 72
__global__ void __launch_bounds__(256, 2) gemm_mma(
    const float* __restrict__ A,
    const __nv_bfloat16* __restrict__ Bhi,
    const __nv_bfloat16* __restrict__ Blo,
    const float* __restrict__ bias,
    float* __restrict__ C) {
    extern __shared__ __nv_bfloat16 sm[];
    __nv_bfloat16* As_hi = sm;                        // 128*72
    __nv_bfloat16* As_lo = As_hi + 128 * LDS_STRIDE;
    __nv_bfloat16* Bs_hi = As_lo + 128 * LDS_STRIDE;
    __nv_bfloat16* Bs_lo = Bs_hi + 128 * LDS_STRIDE;
    float* s_bias = reinterpret_cast<float*>(Bs_lo + 128 * LDS_STRIDE);

    const int tid = threadIdx.x;
    const int wid = tid >> 5;
    const int lane = tid & 31;
    const int rowBase = blockIdx.y * 128;
    const int colBase = blockIdx.x * 128;
    const int warpRow = (wid >> 2) * 64;  // 0 or 64
    const int warpCol = (wid & 3) * 32;   // 0,32,64,96

    if (tid < 128) s_bias[tid] = bias[colBase + tid];

    float acc[4][4][4];
#pragma unroll
    for (int i = 0; i < 4; i++)
#pragma unroll
        for (int j = 0; j < 4; j++)
#pragma unroll
            for (int r = 0; r < 4; r++) acc[i][j][r] = 0.0f;

    const int a_row = warpRow + (lane & 7) + (lane & 8);
    const int a_col = (lane >> 4) * 8;
    const uint32_t a_hi_base = smem_u32(As_hi) + (a_row * LDS_STRIDE + a_col) * 2;
    const uint32_t a_lo_base = smem_u32(As_lo) + (a_row * LDS_STRIDE + a_col) * 2;
    const int b_row = warpCol + (lane & 7);
    const int b_col = ((lane >> 3) & 1) * 8;
    const uint32_t b_hi_base = smem_u32(Bs_hi) + (b_row * LDS_STRIDE + b_col) * 2;
    const uint32_t b_lo_base = smem_u32(Bs_lo) + (b_row * LDS_STRIDE + b_col) * 2;

    for (int c = 0; c < 4; c++) {
        const int k0 = c * 64;
        __syncthreads();
        // ---- A chunk: 128x64 fp32 -> hi/lo bf16 ----
#pragma unroll
        for (int it = 0; it < 8; it++) {
            int i = it * 256 + tid;
            int row = i >> 4, col = (i & 15) * 4;
            float4 v = *reinterpret_cast<const float4*>(
                &A[(size_t)(rowBase + row) * 256 + k0 + col]);
            __nv_bfloat16 h0 = __float2bfloat16_rn(v.x);
            __nv_bfloat16 h1 = __float2bfloat16_rn(v.y);
            __nv_bfloat16 h2 = __float2bfloat16_rn(v.z);
            __nv_bfloat16 h3 = __float2bfloat16_rn(v.w);
            __nv_bfloat16 l0 = __float2bfloat16_rn(v.x - __bfloat162float(h0));
            __nv_bfloat16 l1 = __float2bfloat16_rn(v.y - __bfloat162float(h1));
            __nv_bfloat16 l2 = __float2bfloat16_rn(v.z - __bfloat162float(h2));
            __nv_bfloat16 l3 = __float2bfloat16_rn(v.w - __bfloat162float(h3));
            uint2 hw, lw;
            hw.x = (uint32_t)__bfloat16_as_ushort(h0) |
                   ((uint32_t)__bfloat16_as_ushort(h1) << 16);
            hw.y = (uint32_t)__bfloat16_as_ushort(h2) |
                   ((uint32_t)__bfloat16_as_ushort(h3) << 16);
            lw.x = (uint32_t)__bfloat16_as_ushort(l0) |
                   ((uint32_t)__bfloat16_as_ushort(l1) << 16);
            lw.y = (uint32_t)__bfloat16_as_ushort(l2) |
                   ((uint32_t)__bfloat16_as_ushort(l3) << 16);
            *reinterpret_cast<uint2*>(&As_hi[row * LDS_STRIDE + col]) = hw;
            *reinterpret_cast<uint2*>(&As_lo[row * LDS_STRIDE + col]) = lw;
        }
        // ---- B chunk ----
#pragma unroll
        for (int it = 0; it < 4; it++) {
            int i = it * 256 + tid;
            int n = i >> 3, col = (i & 7) * 8;
            uint4 hv = *reinterpret_cast<const uint4*>(
                &Bhi[(size_t)(colBase + n) * 256 + k0 + col]);
            uint4 lv = *reinterpret_cast<const uint4*>(
                &Blo[(size_t)(colBase + n) * 256 + k0 + col]);
            *reinterpret_cast<uint4*>(&Bs_hi[n * LDS_STRIDE + col]) = hv;
            *reinterpret_cast<uint4*>(&Bs_lo[n * LDS_STRIDE + col]) = lv;
        }
        __syncthreads();

#pragma unroll
        for (int ks = 0; ks < 4; ks++) {
            const uint32_t kof = ks * 16 * 2;
            uint32_t bh[4][2], bl[4][2];
#pragma unroll
            for (int j = 0; j < 4; j++) {
                LDSM_X2(bh[j][0], bh[j][1], b_hi_base + j * (8 * LDS_STRIDE * 2) + kof);
                LDSM_X2(bl[j][0], bl[j][1], b_lo_base + j * (8 * LDS_STRIDE * 2) + kof);
            }
#pragma unroll
            for (int i = 0; i < 4; i++) {
                uint32_t ah[4], al[4];
                LDSM_X4(ah[0], ah[1], ah[2], ah[3],
                        a_hi_base + i * (16 * LDS_STRIDE * 2) + kof);
                LDSM_X4(al[0], al[1], al[2], al[3],
                        a_lo_base + i * (16 * LDS_STRIDE * 2) + kof);
#pragma unroll
                for (int j = 0; j < 4; j++) {
                    MMA16816(acc[i][j], ah, bh[j]);
                    MMA16816(acc[i][j], ah, bl[j]);
                    MMA16816(acc[i][j], al, bh[j]);
                }
            }
        }
    }

    const int g = lane >> 2, c2 = (lane & 3) * 2;
#pragma unroll
    for (int i = 0; i < 4; i++) {
        int r0 = rowBase + warpRow + i * 16 + g;
#pragma unroll
        for (int j = 0; j < 4; j++) {
            int col = warpCol + j * 8 + c2;
            float b0 = s_bias[col], b1 = s_bias[col + 1];
            float2 o0 = make_float2(acc[i][j][0] + b0, acc[i][j][1] + b1);
            float2 o1 = make_float2(acc[i][j][2] + b0, acc[i][j][3] + b1);
            *reinterpret_cast<float2*>(&C[(size_t)r0 * 256 + colBase + col]) = o0;
            *reinterpret_cast<float2*>(&C[(size_t)(r0 + 8) * 256 + colBase + col]) = o1;
        }
    }
}

// ===========================================================================
// Fused off+attn projection (exact fp32, identical accumulation order to the
// validated sgemm: ascending k0 chunks of 16, inner k 0..15, acc += a*b).
// C[M][96] = query @ [W_off | W_attn] + [b_off | b_attn]
// BM=128, BN=96, BK=16, TM=8, TN=6, 256 threads, register prefetch.
// ===========================================================================
__global__ void __launch_bounds__(256) proj_fused(
    const float* __restrict__ A,
    const float* __restrict__ Woff,   // [256][64]
    const float* __restrict__ boff,   // [64]
    const float* __restrict__ Wattn,  // [256][32]
    const float* __restrict__ battn,  // [32]
    float* __restrict__ C) {          // [M][96]
    __shared__ float As[16][128];
    __shared__ float Bs[16][96];
    __shared__ float s_bias[96];

    const int tid = threadIdx.x;
    const int tx = tid % 16;          // 16 col groups (TN=6)
    const int ty = tid / 16;          // 16 row groups (TM=8)
    const int rowBase = blockIdx.x * 128;

    if (tid < 96) s_bias[tid] = (tid < 64) ? boff[tid] : battn[tid - 64];

    float acc[8][6];
#pragma unroll
    for (int i = 0; i < 8; i++)
#pragma unroll
        for (int j = 0; j < 6; j++) acc[i][j] = 0.0f;

    // prefetch registers
    float4 pa0, pa1, pb0, pb1;
    const bool hasB1 = (tid < 128);
    const int ia0 = tid * 4, ia1 = tid * 4 + 1024;      // A: 2048 floats
    const int ib0 = tid * 4, ib1 = tid * 4 + 1024;      // B: 1536 floats

    auto loadA = [&](int k0, int i) -> float4 {
        int r = i >> 4, c = i & 15;
        return *reinterpret_cast<const float4*>(
            &A[(size_t)(rowBase + r) * 256 + k0 + c]);
    };
    auto loadB = [&](int k0, int i) -> float4 {
        int r = i / 96, c = i % 96;
        const float* p = (c < 64) ? &Woff[(size_t)(k0 + r) * 64 + c]
                                  : &Wattn[(size_t)(k0 + r) * 32 + (c - 64)];
        return *reinterpret_cast<const float4*>(p);
    };

    // prologue: chunk 0
    pa0 = loadA(0, ia0);
    pa1 = loadA(0, ia1);
    pb0 = loadB(0, ib0);
    if (hasB1) pb1 = loadB(0, ib1);

    for (int ch = 0; ch < 16; ch++) {
        __syncthreads();
        // store prefetched tile (A transposed)
        {
            int r = ia0 >> 4, c = ia0 & 15;
            As[c + 0][r] = pa0.x; As[c + 1][r] = pa0.y;
            As[c + 2][r] = pa0.z; As[c + 3][r] = pa0.w;
            r = ia1 >> 4; c = ia1 & 15;
            As[c + 0][r] = pa1.x; As[c + 1][r] = pa1.y;
            As[c + 2][r] = pa1.z; As[c + 3][r] = pa1.w;
            *reinterpret_cast<float4*>(&Bs[ib0 / 96][ib0 % 96]) = pb0;
            if (hasB1)
                *reinterpret_cast<float4*>(&Bs[ib1 / 96][ib1 % 96]) = pb1;
        }
        __syncthreads();

        // prefetch next chunk (overlaps compute below)
        if (ch + 1 < 16) {
            int k0 = (ch + 1) * 16;
            pa0 = loadA(k0, ia0);
            pa1 = loadA(k0, ia1);
            pb0 = loadB(k0, ib0);
            if (hasB1) pb1 = loadB(k0, ib1);
        }

        // compute chunk ch (accumulation order identical to validated kernel)
#pragma unroll
        for (int k = 0; k < 16; k++) {
            float aR[8], bR[6];
#pragma unroll
            for (int i = 0; i < 8; i++) aR[i] = As[k][ty * 8 + i];
#pragma unroll
            for (int j = 0; j < 6; j++) bR[j] = Bs[k][tx * 6 + j];
#pragma unroll
            for (int i = 0; i < 8; i++)
#pragma unroll
                for (int j = 0; j < 6; j++) acc[i][j] += aR[i] * bR[j];
        }
    }

#pragma unroll
    for (int i = 0; i < 8; i++) {
        int r = rowBase + ty * 8 + i;
#pragma unroll
        for (int j = 0; j < 6; j++) {
            int c = tx * 6 + j;
            C[(size_t)r * 96 + c] = acc[i][j] + s_bias[c];
        }
    }
}

// ---------------------------------------------------------------------------
// Sampling kernel — reads fused projection [q][96]: off at 0..63, attn 64..95
// ---------------------------------------------------------------------------
__global__ void sample_kernel(const float* __restrict__ refp,
                              const float* __restrict__ proj,
                              const float* __restrict__ v,
                              float* __restrict__ outw) {
    const int warpsPerBlock = blockDim.x >> 5;
    const int q = blockIdx.x * warpsPerBlock + (threadIdx.x >> 5);
    const int lane = threadIdx.x & 31;
    if (q >= BB * NN) return;
    const int b = q >> 14;

    const float* prow = proj + (size_t)q * 96;
    float logit = prow[64 + lane];
    float m = logit;
    m = fmaxf(m, __shfl_xor_sync(0xffffffffu, m, 1));
    m = fmaxf(m, __shfl_xor_sync(0xffffffffu, m, 2));
    float e = expf(logit - m);
    float s = e;
    s += __shfl_xor_sync(0xffffffffu, s, 1);
    s += __shfl_xor_sync(0xffffffffu, s, 2);
    float w = e / s;

    float rx = refp[(size_t)q * 2 + 0];
    float ry = refp[(size_t)q * 2 + 1];
    float ox = prow[lane * 2 + 0];
    float oy = prow[lane * 2 + 1];
    float lx = (rx + ox) * 2.0f - 1.0f;
    float ly = (ry + oy) * 2.0f - 1.0f;
    float fx = (lx + 1.0f) * 64.0f - 0.5f;
    float fy = (ly + 1.0f) * 64.0f - 0.5f;
    float ixf = rintf(fx);
    float iyf = rintf(fy);
    bool valid = (ixf >= 0.0f) && (ixf < 128.0f) && (iyf >= 0.0f) && (iyf < 128.0f);
    int flat = valid ? ((int)iyf * 128 + (int)ixf) : 0;
    float wv = valid ? w : 0.0f;

    const float* vb = v + (size_t)b * NVV * DD;
    const size_t outBase = (size_t)q * DD;
#pragma unroll
    for (int h = 0; h < NHH; h++) {
        float acc = 0.0f;
#pragma unroll
        for (int p = 0; p < PP; p++) {
            int src = h * 4 + p;
            float ww = __shfl_sync(0xffffffffu, wv, src);
            int fl = __shfl_sync(0xffffffffu, flat, src);
            if (ww != 0.0f) {
                acc += ww * vb[(size_t)fl * DD + h * 32 + lane];
            }
        }
        outw[outBase + h * 32 + lane] = acc;
    }
}

// ---------------------------------------------------------------------------
extern "C" void kernel_launch(void* const* d_in, const int* in_sizes, int n_in,
                              void* d_out, int out_size) {
    const float* query  = (const float*)d_in[0];
    const float* refp   = (const float*)d_in[1];
    const float* value  = (const float*)d_in[2];
    const float* W_off  = (const float*)d_in[3];
    const float* b_off  = (const float*)d_in[4];
    const float* W_attn = (const float*)d_in[5];
    const float* b_attn = (const float*)d_in[6];
    const float* W_v    = (const float*)d_in[7];
    const float* b_v    = (const float*)d_in[8];
    const float* W_out  = (const float*)d_in[9];
    const float* b_out  = (const float*)d_in[10];
    float* out = (float*)d_out;

    float *gv = nullptr, *gw = nullptr, *gp = nullptr;
    __nv_bfloat16 *wvh = nullptr, *wvl = nullptr, *woh = nullptr, *wol = nullptr;
    cudaGetSymbolAddress((void**)&gv, g_v);
    cudaGetSymbolAddress((void**)&gw, g_weighted);
    cudaGetSymbolAddress((void**)&gp, g_proj);
    cudaGetSymbolAddress((void**)&wvh, g_wv_hi);
    cudaGetSymbolAddress((void**)&wvl, g_wv_lo);
    cudaGetSymbolAddress((void**)&woh, g_wo_hi);
    cudaGetSymbolAddress((void**)&wol, g_wo_lo);

    const int M = BB * NN;  // 65536
    const int SMEM = 4 * 128 * LDS_STRIDE * 2 + 128 * 4;  // 74240
    cudaFuncSetAttribute(gemm_mma, cudaFuncAttributeMaxDynamicSharedMemorySize,
                         SMEM);

    // 0. prep bf16-split transposed weights
    prep_weight<<<256, 256>>>(W_v, wvh, wvl, 256);
    prep_weight<<<256, 256>>>(W_out, woh, wol, 256);

    // 1. v = value @ W_v + b_v (tensor cores, bf16x3)
    gemm_mma<<<dim3(2, M / 128), 256, SMEM>>>(value, wvh, wvl, b_v, gv);

    // 2. fused off+attn projection — EXACT fp32, same accumulation order
    proj_fused<<<M / 128, 256>>>(query, W_off, b_off, W_attn, b_attn, gp);

    // 3. softmax + nearest gather + weighted sum
    sample_kernel<<<M / 8, 256>>>(refp, gp, gv, gw);

    // 4. out = weighted @ W_out + b_out (tensor cores, bf16x3)
    gemm_mma<<<dim3(2, M / 128), 256, SMEM>>>(gw, woh, wol, b_out, out);
}